// round 14
// baseline (speedup 1.0000x reference)
#include <cuda_runtime.h>

#define DIM 128
#define DIM4 32
#define MAX_NODES 50000
#define MAX_EDGES 800000
#define CAP 96

// ---- device scratch (allocation-free rule: __device__ globals; zero-init) --
__device__ float              g_HW[(size_t)MAX_NODES * DIM];      // 25.6 MB
__device__ unsigned long long g_bin[(size_t)MAX_NODES * CAP];     // 38.4 MB
__device__ int                g_cnt[MAX_NODES];                   // self-cleaning
__device__ int                g_ovf_cnt;                          // self-cleaning
__device__ int                g_ovf_n;                            // snapshot for ovf
__device__ int                g_ovf_r[MAX_EDGES];
__device__ unsigned long long g_ovf_e[MAX_EDGES];

#define EDGES_PER_BIN_BLOCK 512
#define KT 64   // k-tile width (two phases cover DIM=128)

// smem: sW [KT][128] = 32KB, sHT [KT k][64 rows] = 16KB  -> 48KB, 4 CTAs/SM
#define SMEM_FLOATS (KT * DIM + KT * 64)

// ---------------------------------------------------------------------------
// Fused kernel: blocks [0, n_gemm_blocks) run the GEMM path (64 rows/block,
// FFMA2, k-tiled 48KB smem, 8 rows/warp); blocks [n_gemm_blocks, ...) bin
// 512 edges each. Phases are data-independent; fusion overlaps them.
// ---------------------------------------------------------------------------
__global__ void __launch_bounds__(256, 4) fused_gemm_bin_kernel(
        const float* __restrict__ H, const float* __restrict__ W,
        const int* __restrict__ rows, const int* __restrict__ cols,
        const float* __restrict__ vals,
        int n_nodes, int n_edges, int n_gemm_blocks) {
    if ((int)blockIdx.x >= n_gemm_blocks) {
        // ---------------- bin path ----------------
        int base = ((int)blockIdx.x - n_gemm_blocks) * EDGES_PER_BIN_BLOCK
                 + (int)threadIdx.x;
#pragma unroll
        for (int t = 0; t < EDGES_PER_BIN_BLOCK / 256; t++) {
            int e = base + t * 256;
            if (e < n_edges) {
                int r = rows[e];
                unsigned long long pk = (unsigned long long)(unsigned)cols[e]
                    | ((unsigned long long)__float_as_uint(vals[e]) << 32);
                int p = atomicAdd(&g_cnt[r], 1);
                if (p < CAP) {
                    g_bin[(size_t)r * CAP + p] = pk;
                } else {
                    int q = atomicAdd(&g_ovf_cnt, 1);
                    g_ovf_r[q] = r;
                    g_ovf_e[q] = pk;
                }
            }
        }
        return;
    }

    // ---------------- GEMM path: g_HW = H @ W (FFMA2, k-tiled) ----------------
    extern __shared__ float smem[];
    float* sW  = smem;             // [KT][128]
    float* sHT = smem + KT * DIM;  // [KT k][64 rows] (transposed)

    const int tid  = threadIdx.x;
    const int row0 = (int)blockIdx.x * 64;
    const int tr   = tid >> 5;     // warp -> rows tr*8 .. tr*8+7
    const int tc   = tid & 31;     // lane -> cols tc*4 .. tc*4+3

    unsigned long long acc[4][4];  // [row-pair][col] packed (row 2p, row 2p+1)
#pragma unroll
    for (int p = 0; p < 4; p++)
#pragma unroll
        for (int j = 0; j < 4; j++) acc[p][j] = 0ull;

    for (int kh = 0; kh < DIM; kh += KT) {
        __syncthreads();
        // load W k-slice: KT rows x 32 float4 = 2048 float4, 8 per thread
        for (int i = tid; i < KT * DIM4; i += 256) {
            int kk = i / DIM4;
            ((float4*)sW)[i] = ((const float4*)W)[(kh + kk) * DIM4 + (i % DIM4)];
        }
        // load H tile k-slice transposed: 64 rows x KT k = 1024 float4
        for (int i = tid; i < 64 * (KT / 4); i += 256) {
            int r  = i / (KT / 4);
            int k4 = (i % (KT / 4)) * 4;
            int rr = row0 + r;
            float4 v = make_float4(0.f, 0.f, 0.f, 0.f);
            if (rr < n_nodes)
                v = ((const float4*)H)[(size_t)rr * DIM4 + (kh + k4) / 4];
            sHT[(k4 + 0) * 64 + r] = v.x;
            sHT[(k4 + 1) * 64 + r] = v.y;
            sHT[(k4 + 2) * 64 + r] = v.z;
            sHT[(k4 + 3) * 64 + r] = v.w;
        }
        __syncthreads();

#pragma unroll 2
        for (int k = 0; k < KT; k++) {
            float4 w = ((const float4*)sW)[k * DIM4 + tc];
            unsigned long long ws0, ws1, ws2, ws3;
            asm("mov.b64 %0, {%1, %2};" : "=l"(ws0) : "f"(w.x), "f"(w.x));
            asm("mov.b64 %0, {%1, %2};" : "=l"(ws1) : "f"(w.y), "f"(w.y));
            asm("mov.b64 %0, {%1, %2};" : "=l"(ws2) : "f"(w.z), "f"(w.z));
            asm("mov.b64 %0, {%1, %2};" : "=l"(ws3) : "f"(w.w), "f"(w.w));
            // 8 h rows for this warp via 2 broadcast LDS.128 (half the
            // crossbar wavefronts of 4x LDS.64)
            const float4* hbase = (const float4*)&sHT[k * 64 + tr * 8];
            float4 hq0 = hbase[0];   // rows r..r+3
            float4 hq1 = hbase[1];   // rows r+4..r+7
            unsigned long long hp0 = *(unsigned long long*)&hq0.x;
            unsigned long long hp1 = *(unsigned long long*)&hq0.z;
            unsigned long long hp2 = *(unsigned long long*)&hq1.x;
            unsigned long long hp3 = *(unsigned long long*)&hq1.z;
            asm("fma.rn.f32x2 %0, %1, %2, %0;" : "+l"(acc[0][0]) : "l"(hp0), "l"(ws0));
            asm("fma.rn.f32x2 %0, %1, %2, %0;" : "+l"(acc[0][1]) : "l"(hp0), "l"(ws1));
            asm("fma.rn.f32x2 %0, %1, %2, %0;" : "+l"(acc[0][2]) : "l"(hp0), "l"(ws2));
            asm("fma.rn.f32x2 %0, %1, %2, %0;" : "+l"(acc[0][3]) : "l"(hp0), "l"(ws3));
            asm("fma.rn.f32x2 %0, %1, %2, %0;" : "+l"(acc[1][0]) : "l"(hp1), "l"(ws0));
            asm("fma.rn.f32x2 %0, %1, %2, %0;" : "+l"(acc[1][1]) : "l"(hp1), "l"(ws1));
            asm("fma.rn.f32x2 %0, %1, %2, %0;" : "+l"(acc[1][2]) : "l"(hp1), "l"(ws2));
            asm("fma.rn.f32x2 %0, %1, %2, %0;" : "+l"(acc[1][3]) : "l"(hp1), "l"(ws3));
            asm("fma.rn.f32x2 %0, %1, %2, %0;" : "+l"(acc[2][0]) : "l"(hp2), "l"(ws0));
            asm("fma.rn.f32x2 %0, %1, %2, %0;" : "+l"(acc[2][1]) : "l"(hp2), "l"(ws1));
            asm("fma.rn.f32x2 %0, %1, %2, %0;" : "+l"(acc[2][2]) : "l"(hp2), "l"(ws2));
            asm("fma.rn.f32x2 %0, %1, %2, %0;" : "+l"(acc[2][3]) : "l"(hp2), "l"(ws3));
            asm("fma.rn.f32x2 %0, %1, %2, %0;" : "+l"(acc[3][0]) : "l"(hp3), "l"(ws0));
            asm("fma.rn.f32x2 %0, %1, %2, %0;" : "+l"(acc[3][1]) : "l"(hp3), "l"(ws1));
            asm("fma.rn.f32x2 %0, %1, %2, %0;" : "+l"(acc[3][2]) : "l"(hp3), "l"(ws2));
            asm("fma.rn.f32x2 %0, %1, %2, %0;" : "+l"(acc[3][3]) : "l"(hp3), "l"(ws3));
        }
    }

#pragma unroll
    for (int p = 0; p < 4; p++) {
        float2 a0 = *reinterpret_cast<float2*>(&acc[p][0]);
        float2 a1 = *reinterpret_cast<float2*>(&acc[p][1]);
        float2 a2 = *reinterpret_cast<float2*>(&acc[p][2]);
        float2 a3 = *reinterpret_cast<float2*>(&acc[p][3]);
        int rr0 = row0 + tr * 8 + 2 * p;
        int rr1 = rr0 + 1;
        if (rr0 < n_nodes)
            ((float4*)g_HW)[(size_t)rr0 * DIM4 + tc] = make_float4(a0.x, a1.x, a2.x, a3.x);
        if (rr1 < n_nodes)
            ((float4*)g_HW)[(size_t)rr1 * DIM4 + tc] = make_float4(a0.y, a1.y, a2.y, a3.y);
    }
}

// ---------------------------------------------------------------------------
// SpMM: one warp per output row (R3-proven form: broadcast LDG of bin entries,
// unroll-4 gathers; runs at the LTS bandwidth cap).
// ---------------------------------------------------------------------------
__global__ void __launch_bounds__(256) spmm_kernel(const float* __restrict__ bias,
                                                   float* __restrict__ out,
                                                   int n_nodes) {
    int gt   = blockIdx.x * blockDim.x + threadIdx.x;
    int r    = gt >> 5;
    int lane = gt & 31;
    if (r >= n_nodes) return;

    int cnt = g_cnt[r];
    if (lane == 0) g_cnt[r] = 0;                 // self-clean for next replay
    if (r == 0 && lane == 0) {                   // snapshot + reset overflow count
        g_ovf_n = g_ovf_cnt;
        g_ovf_cnt = 0;
    }
    int n = cnt > CAP ? CAP : cnt;
    const unsigned long long* bp = &g_bin[(size_t)r * CAP];

    float4 acc = ((const float4*)bias)[lane];
#pragma unroll 4
    for (int j = 0; j < n; j++) {
        unsigned long long e = bp[j];
        int   c = (int)(unsigned)e;
        float v = __uint_as_float((unsigned)(e >> 32));
        float4 hw = ((const float4*)g_HW)[(size_t)c * DIM4 + lane];
        acc.x += v * hw.x;
        acc.y += v * hw.y;
        acc.z += v * hw.z;
        acc.w += v * hw.w;
    }
    ((float4*)out)[(size_t)r * DIM4 + lane] = acc;
}

// ---------------------------------------------------------------------------
// Overflow edges (empty in practice; correctness path). Runs after spmm.
// ---------------------------------------------------------------------------
__global__ void __launch_bounds__(256) ovf_kernel(float* __restrict__ out) {
    int n = g_ovf_n;
    if (n <= 0) return;
    int warps = (gridDim.x * blockDim.x) >> 5;
    int w     = (blockIdx.x * blockDim.x + threadIdx.x) >> 5;
    int lane  = threadIdx.x & 31;
    for (int i = w; i < n; i += warps) {
        int r = g_ovf_r[i];
        unsigned long long e = g_ovf_e[i];
        int   c = (int)(unsigned)e;
        float v = __uint_as_float((unsigned)(e >> 32));
        float4 hw = ((const float4*)g_HW)[(size_t)c * DIM4 + lane];
        float* p = out + (size_t)r * DIM + lane * 4;
        asm volatile("red.global.add.v4.f32 [%0], {%1, %2, %3, %4};"
                     :: "l"(p), "f"(v * hw.x), "f"(v * hw.y), "f"(v * hw.z), "f"(v * hw.w)
                     : "memory");
    }
}

// ---------------------------------------------------------------------------
// Launch. Inputs: edge_rows, edge_cols, edge_vals, H, W, bias. Output f32.
// ---------------------------------------------------------------------------
extern "C" void kernel_launch(void* const* d_in, const int* in_sizes, int n_in,
                              void* d_out, int out_size) {
    const int*   edge_rows = (const int*)d_in[0];
    const int*   edge_cols = (const int*)d_in[1];
    const float* edge_vals = (const float*)d_in[2];
    const float* H         = (const float*)d_in[3];
    const float* W         = (const float*)d_in[4];
    const float* bias      = (const float*)d_in[5];
    float*       out       = (float*)d_out;

    const int n_edges = in_sizes[0];
    const int n_nodes = in_sizes[3] / DIM;

    const int smem_bytes = SMEM_FLOATS * (int)sizeof(float);  // 48 KB
    cudaFuncSetAttribute(fused_gemm_bin_kernel,
                         cudaFuncAttributeMaxDynamicSharedMemorySize, smem_bytes);

    // 1) fused: GEMM (g_HW = H @ W) in blocks [0, gb), edge binning after
    const int gemm_blocks = (n_nodes + 63) / 64;
    const int bin_blocks  = (n_edges + EDGES_PER_BIN_BLOCK - 1) / EDGES_PER_BIN_BLOCK;
    fused_gemm_bin_kernel<<<gemm_blocks + bin_blocks, 256, smem_bytes>>>(
        H, W, edge_rows, edge_cols, edge_vals, n_nodes, n_edges, gemm_blocks);

    // 2) out = bias + row-gathered sum (no atomics), self-cleans counters
    {
        long long threads = (long long)n_nodes * 32;
        spmm_kernel<<<(int)((threads + 255) / 256), 256>>>(bias, out, n_nodes);
    }

    // 3) overflow correctness path (empty in practice)
    ovf_kernel<<<16, 256>>>(out);
}

// round 16
// speedup vs baseline: 1.2904x; 1.2904x over previous
#include <cuda_runtime.h>
#include <cuda_bf16.h>
#include <cstdint>

#define DIM 128
#define DIM4 32
#define MAX_NODES 50000
#define MAX_EDGES 800000
#define CAP 96
#define EDGES_PER_BIN_BLOCK 512

#define TILE_M 128
#define KT 64            // k per phase (2 phases cover K=128)
#define SSTRIDE 72       // smem row stride in bf16 (bank-conflict-free)

// smem: Ahi, Alo, Bhi, Blo each 128 x SSTRIDE bf16 = 18432 B -> 73728 B total
#define SMEM_BYTES (4 * 128 * SSTRIDE * 2)

// ---- device scratch (allocation-free rule: __device__ globals; zero-init) --
__device__ float              g_HW[(size_t)MAX_NODES * DIM];
__device__ unsigned long long g_bin[(size_t)MAX_NODES * CAP];
__device__ int                g_cnt[MAX_NODES];
__device__ int                g_ovf_cnt;
__device__ int                g_ovf_n;
__device__ int                g_ovf_r[MAX_EDGES];
__device__ unsigned long long g_ovf_e[MAX_EDGES];
// W^T split into bf16 hi/lo, plain [n][k] layout (n-major, k contiguous)
__device__ __align__(16) unsigned short g_WT_hi[DIM * DIM];
__device__ __align__(16) unsigned short g_WT_lo[DIM * DIM];

__device__ __forceinline__ uint32_t pack_bf16(__nv_bfloat16 a, __nv_bfloat16 b) {
    return (uint32_t)__bfloat16_as_ushort(a) | ((uint32_t)__bfloat16_as_ushort(b) << 16);
}

__device__ __forceinline__ void mma16816(float* d, uint32_t a0, uint32_t a1,
                                         uint32_t a2, uint32_t a3,
                                         uint32_t b0, uint32_t b1) {
    asm volatile(
        "mma.sync.aligned.m16n8k16.row.col.f32.bf16.bf16.f32 "
        "{%0,%1,%2,%3}, {%4,%5,%6,%7}, {%8,%9}, {%0,%1,%2,%3};"
        : "+f"(d[0]), "+f"(d[1]), "+f"(d[2]), "+f"(d[3])
        : "r"(a0), "r"(a1), "r"(a2), "r"(a3), "r"(b0), "r"(b1));
}

// ---------------------------------------------------------------------------
// Prep: W [k][n] -> W^T hi/lo bf16 images [n][k]
// ---------------------------------------------------------------------------
__global__ void prep_w_kernel(const float* __restrict__ W) {
    int idx = blockIdx.x * blockDim.x + threadIdx.x;
    if (idx >= DIM * DIM) return;
    int k = idx >> 7, n = idx & 127;
    float x = W[idx];
    __nv_bfloat16 h = __float2bfloat16_rn(x);
    __nv_bfloat16 l = __float2bfloat16_rn(x - __bfloat162float(h));
    g_WT_hi[n * DIM + k] = __bfloat16_as_ushort(h);
    g_WT_lo[n * DIM + k] = __bfloat16_as_ushort(l);
}

// ---------------------------------------------------------------------------
// Fused: blocks [0, ngb) = bf16x3 mma.sync GEMM tiles (128 rows x 128 cols);
//        blocks [ngb, ...) = edge binning (512 edges each). Overlapped.
// ---------------------------------------------------------------------------
__global__ void __launch_bounds__(256, 2) fused_gemm_bin_kernel(
        const float* __restrict__ H,
        const int* __restrict__ rows, const int* __restrict__ cols,
        const float* __restrict__ vals,
        int n_nodes, int n_edges, int n_gemm_blocks) {
    if ((int)blockIdx.x >= n_gemm_blocks) {
        // ---------------- bin path ----------------
        int base = ((int)blockIdx.x - n_gemm_blocks) * EDGES_PER_BIN_BLOCK
                 + (int)threadIdx.x;
#pragma unroll
        for (int t = 0; t < EDGES_PER_BIN_BLOCK / 256; t++) {
            int e = base + t * 256;
            if (e < n_edges) {
                int r = rows[e];
                unsigned long long pk = (unsigned long long)(unsigned)cols[e]
                    | ((unsigned long long)__float_as_uint(vals[e]) << 32);
                int p = atomicAdd(&g_cnt[r], 1);
                if (p < CAP) {
                    g_bin[(size_t)r * CAP + p] = pk;
                } else {
                    int q = atomicAdd(&g_ovf_cnt, 1);
                    g_ovf_r[q] = r;
                    g_ovf_e[q] = pk;
                }
            }
        }
        return;
    }

    // ---------------- GEMM path ----------------
    extern __shared__ char smem[];
    __nv_bfloat16* sAhi = (__nv_bfloat16*)smem;                 // [128][SSTRIDE]
    __nv_bfloat16* sAlo = sAhi + 128 * SSTRIDE;
    __nv_bfloat16* sBhi = sAlo + 128 * SSTRIDE;                 // [n][k]
    __nv_bfloat16* sBlo = sBhi + 128 * SSTRIDE;

    const int tid  = threadIdx.x;
    const int wid  = tid >> 5;
    const int lane = tid & 31;
    const int g    = lane >> 2;       // 0..7
    const int tg   = lane & 3;        // 0..3
    const int row0 = (int)blockIdx.x * TILE_M;

    // warp tile: rows r0..r0+31 (two 16-row tiles), cols c0..c0+63 (8 n-tiles)
    const int r0 = (wid & 3) * 32;
    const int c0 = (wid >> 2) * 64;

    float acc[2][8][4];
#pragma unroll
    for (int rt = 0; rt < 2; rt++)
#pragma unroll
        for (int nt = 0; nt < 8; nt++)
#pragma unroll
            for (int j = 0; j < 4; j++) acc[rt][nt][j] = 0.f;

    const float4* H4 = (const float4*)H;

    for (int p = 0; p < 2; p++) {
        __syncthreads();   // previous phase's fragment loads complete

        // A slice: H rows [row0, row0+128), k-half p -> bf16 hi/lo, padded
        for (int i = tid; i < 128 * (KT / 4); i += 256) {
            int r = i >> 4;
            int q = i & 15;
            int rr = row0 + r;
            float4 v = make_float4(0.f, 0.f, 0.f, 0.f);
            if (rr < n_nodes) v = H4[(size_t)rr * 32 + p * 16 + q];
            __nv_bfloat16 h0 = __float2bfloat16_rn(v.x);
            __nv_bfloat16 h1 = __float2bfloat16_rn(v.y);
            __nv_bfloat16 h2 = __float2bfloat16_rn(v.z);
            __nv_bfloat16 h3 = __float2bfloat16_rn(v.w);
            __nv_bfloat16 l0 = __float2bfloat16_rn(v.x - __bfloat162float(h0));
            __nv_bfloat16 l1 = __float2bfloat16_rn(v.y - __bfloat162float(h1));
            __nv_bfloat16 l2 = __float2bfloat16_rn(v.z - __bfloat162float(h2));
            __nv_bfloat16 l3 = __float2bfloat16_rn(v.w - __bfloat162float(h3));
            uint2* dh = (uint2*)&sAhi[r * SSTRIDE + q * 4];
            uint2* dl = (uint2*)&sAlo[r * SSTRIDE + q * 4];
            *dh = make_uint2(pack_bf16(h0, h1), pack_bf16(h2, h3));
            *dl = make_uint2(pack_bf16(l0, l1), pack_bf16(l2, l3));
        }
        // B slices: g_WT_{hi,lo}[n][p*64 + k] -> smem padded [n][k]
        for (int i = tid; i < 128 * (KT / 4); i += 256) {
            int n = i >> 4;
            int q = i & 15;
            uint2 vh = *(const uint2*)&g_WT_hi[n * DIM + p * KT + q * 4];
            uint2 vl = *(const uint2*)&g_WT_lo[n * DIM + p * KT + q * 4];
            *(uint2*)&sBhi[n * SSTRIDE + q * 4] = vh;
            *(uint2*)&sBlo[n * SSTRIDE + q * 4] = vl;
        }
        __syncthreads();

#pragma unroll
        for (int ks = 0; ks < KT / 16; ks++) {
            const int kk = ks * 16;
            // A fragments for both row tiles, hi and lo
            uint32_t ah[2][4], al[2][4];
#pragma unroll
            for (int rt = 0; rt < 2; rt++) {
                int rb = r0 + rt * 16;
                const __nv_bfloat16* ph = sAhi;
                const __nv_bfloat16* pl = sAlo;
                ah[rt][0] = *(const uint32_t*)&ph[(rb + g)     * SSTRIDE + kk + 2 * tg];
                ah[rt][1] = *(const uint32_t*)&ph[(rb + g + 8) * SSTRIDE + kk + 2 * tg];
                ah[rt][2] = *(const uint32_t*)&ph[(rb + g)     * SSTRIDE + kk + 2 * tg + 8];
                ah[rt][3] = *(const uint32_t*)&ph[(rb + g + 8) * SSTRIDE + kk + 2 * tg + 8];
                al[rt][0] = *(const uint32_t*)&pl[(rb + g)     * SSTRIDE + kk + 2 * tg];
                al[rt][1] = *(const uint32_t*)&pl[(rb + g + 8) * SSTRIDE + kk + 2 * tg];
                al[rt][2] = *(const uint32_t*)&pl[(rb + g)     * SSTRIDE + kk + 2 * tg + 8];
                al[rt][3] = *(const uint32_t*)&pl[(rb + g + 8) * SSTRIDE + kk + 2 * tg + 8];
            }
#pragma unroll
            for (int nt = 0; nt < 8; nt++) {
                int n = c0 + nt * 8 + g;
                uint32_t bh0 = *(const uint32_t*)&sBhi[n * SSTRIDE + kk + 2 * tg];
                uint32_t bh1 = *(const uint32_t*)&sBhi[n * SSTRIDE + kk + 2 * tg + 8];
                uint32_t bl0 = *(const uint32_t*)&sBlo[n * SSTRIDE + kk + 2 * tg];
                uint32_t bl1 = *(const uint32_t*)&sBlo[n * SSTRIDE + kk + 2 * tg + 8];
#pragma unroll
                for (int rt = 0; rt < 2; rt++) {
                    mma16816(acc[rt][nt], ah[rt][0], ah[rt][1], ah[rt][2], ah[rt][3], bh0, bh1);
                    mma16816(acc[rt][nt], ah[rt][0], ah[rt][1], ah[rt][2], ah[rt][3], bl0, bl1);
                    mma16816(acc[rt][nt], al[rt][0], al[rt][1], al[rt][2], al[rt][3], bh0, bh1);
                }
            }
        }
    }

    // Epilogue: D rows (g, g+8), cols (2tg, 2tg+1) per tile; float2 stores
    float2* o = (float2*)g_HW;
#pragma unroll
    for (int rt = 0; rt < 2; rt++) {
#pragma unroll
        for (int nt = 0; nt < 8; nt++) {
            int col  = c0 + nt * 8 + 2 * tg;
            int rowA = row0 + r0 + rt * 16 + g;
            int rowB = rowA + 8;
            if (rowA < n_nodes)
                o[(size_t)rowA * 64 + (col >> 1)] = make_float2(acc[rt][nt][0], acc[rt][nt][1]);
            if (rowB < n_nodes)
                o[(size_t)rowB * 64 + (col >> 1)] = make_float2(acc[rt][nt][2], acc[rt][nt][3]);
        }
    }
}

// ---------------------------------------------------------------------------
// SpMM: one warp per output row (R3-proven form; runs at the LTS cap).
// ---------------------------------------------------------------------------
__global__ void __launch_bounds__(256) spmm_kernel(const float* __restrict__ bias,
                                                   float* __restrict__ out,
                                                   int n_nodes) {
    int gt   = blockIdx.x * blockDim.x + threadIdx.x;
    int r    = gt >> 5;
    int lane = gt & 31;
    if (r >= n_nodes) return;

    int cnt = g_cnt[r];
    if (lane == 0) g_cnt[r] = 0;
    if (r == 0 && lane == 0) { g_ovf_n = g_ovf_cnt; g_ovf_cnt = 0; }
    int n = cnt > CAP ? CAP : cnt;
    const unsigned long long* bp = &g_bin[(size_t)r * CAP];

    float4 acc = ((const float4*)bias)[lane];
#pragma unroll 4
    for (int j = 0; j < n; j++) {
        unsigned long long e = bp[j];
        int   c = (int)(unsigned)e;
        float v = __uint_as_float((unsigned)(e >> 32));
        float4 hw = ((const float4*)g_HW)[(size_t)c * DIM4 + lane];
        acc.x += v * hw.x;
        acc.y += v * hw.y;
        acc.z += v * hw.z;
        acc.w += v * hw.w;
    }
    ((float4*)out)[(size_t)r * DIM4 + lane] = acc;
}

// ---------------------------------------------------------------------------
// Overflow edges (empty in practice; correctness path). Runs after spmm.
// ---------------------------------------------------------------------------
__global__ void __launch_bounds__(256) ovf_kernel(float* __restrict__ out) {
    int n = g_ovf_n;
    if (n <= 0) return;
    int warps = (gridDim.x * blockDim.x) >> 5;
    int w     = (blockIdx.x * blockDim.x + threadIdx.x) >> 5;
    int lane  = threadIdx.x & 31;
    for (int i = w; i < n; i += warps) {
        int r = g_ovf_r[i];
        unsigned long long e = g_ovf_e[i];
        int   c = (int)(unsigned)e;
        float v = __uint_as_float((unsigned)(e >> 32));
        float4 hw = ((const float4*)g_HW)[(size_t)c * DIM4 + lane];
        float* p = out + (size_t)r * DIM + lane * 4;
        asm volatile("red.global.add.v4.f32 [%0], {%1, %2, %3, %4};"
                     :: "l"(p), "f"(v * hw.x), "f"(v * hw.y), "f"(v * hw.z), "f"(v * hw.w)
                     : "memory");
    }
}

// ---------------------------------------------------------------------------
// Launch. Inputs: edge_rows, edge_cols, edge_vals, H, W, bias. Output f32.
// ---------------------------------------------------------------------------
extern "C" void kernel_launch(void* const* d_in, const int* in_sizes, int n_in,
                              void* d_out, int out_size) {
    const int*   edge_rows = (const int*)d_in[0];
    const int*   edge_cols = (const int*)d_in[1];
    const float* edge_vals = (const float*)d_in[2];
    const float* H         = (const float*)d_in[3];
    const float* W         = (const float*)d_in[4];
    const float* bias      = (const float*)d_in[5];
    float*       out       = (float*)d_out;

    const int n_edges = in_sizes[0];
    const int n_nodes = in_sizes[3] / DIM;

    cudaFuncSetAttribute(fused_gemm_bin_kernel,
                         cudaFuncAttributeMaxDynamicSharedMemorySize, SMEM_BYTES);

    // 0) W^T -> bf16 hi/lo images
    prep_w_kernel<<<64, 256>>>(W);

    // 1) fused: tensor-core GEMM tiles + edge binning, overlapped
    const int gemm_blocks = (n_nodes + TILE_M - 1) / TILE_M;
    const int bin_blocks  = (n_edges + EDGES_PER_BIN_BLOCK - 1) / EDGES_PER_BIN_BLOCK;
    fused_gemm_bin_kernel<<<gemm_blocks + bin_blocks, 256, SMEM_BYTES>>>(
        H, edge_rows, edge_cols, edge_vals, n_nodes, n_edges, gemm_blocks);

    // 2) out = bias + row-gathered sum (no atomics), self-cleans counters
    {
        long long threads = (long long)n_nodes * 32;
        spmm_kernel<<<(int)((threads + 255) / 256), 256>>>(bias, out, n_nodes);
    }

    // 3) overflow correctness path (empty in practice)
    ovf_kernel<<<16, 256>>>(out);
}